// round 5
// baseline (speedup 1.0000x reference)
#include <cuda_runtime.h>
#include <math.h>

#define BSZ   4
#define NTOK  1024
#define DIN   384
#define SST   16
#define NROWS 4096
#define NCOLS 816
#define COLS_PAD 832

__device__ __align__(16) float g_wpack[DIN * COLS_PAD];
__device__ __align__(16) float g_bias[COLS_PAD];
__device__ __align__(16) float g_xT[DIN * NROWS];
__device__ __align__(16) float g_scratch[COLS_PAD * NROWS];

__device__ __forceinline__ float softplusf(float z) {
    return (z > 20.f) ? z : log1pf(expf(z));
}

// ---------------- kernel 0a: pack weights k-major + bias ----------------
__global__ void pack_kernel(const float* __restrict__ dtsW, const float* __restrict__ dtsb,
                            const float* __restrict__ dtdW, const float* __restrict__ dtdb,
                            const float* __restrict__ BW,   const float* __restrict__ CrW,
                            const float* __restrict__ CiW) {
    int i = blockIdx.x * blockDim.x + threadIdx.x;
    if (i >= DIN * COLS_PAD) return;
    int k = i / COLS_PAD;
    int c = i % COLS_PAD;
    float v = 0.f;
    if      (c < 384) v = dtsW[c * DIN + k];
    else if (c < 768) v = dtdW[(c - 384) * DIN + k];
    else if (c < 784) v = BW [k * SST + (c - 768)];
    else if (c < 800) v = CrW[k * SST + (c - 784)];
    else if (c < 816) v = CiW[k * SST + (c - 800)];
    g_wpack[i] = v;
    if (k == 0) {
        float bv = 0.f;
        if (c < 384)      bv = dtsb[c];
        else if (c < 768) bv = dtdb[c - 384];
        g_bias[c] = bv;
    }
}

// ---------------- kernel 0b: transpose x -> xT[d][row] ----------------
__global__ void transpose_x(const float* __restrict__ x) {
    __shared__ float tile[32][33];
    int kb = blockIdx.x * 32;
    int rb = blockIdx.y * 32;
    int tx = threadIdx.x, ty = threadIdx.y;
    #pragma unroll
    for (int i = ty; i < 32; i += 8)
        tile[i][tx] = x[(rb + i) * DIN + kb + tx];
    __syncthreads();
    #pragma unroll
    for (int i = ty; i < 32; i += 8)
        g_xT[(kb + i) * NROWS + rb + tx] = tile[tx][i];
}

// ---------------- kernel 1: fused GEMM ----------------
#define GBM 64
#define GBN 128
#define GBK 16
__global__ __launch_bounds__(256) void gemm_kernel() {
    __shared__ float Ws[GBK][68];
    __shared__ float Xs[GBK][GBN + 4];
    int tid = threadIdx.x;
    int tx = tid & 15;
    int ty = tid >> 4;
    int cBase = blockIdx.x * GBM;
    int rBase = blockIdx.y * GBN;

    float acc[4][8];
    #pragma unroll
    for (int i = 0; i < 4; i++)
        #pragma unroll
        for (int j = 0; j < 8; j++) acc[i][j] = 0.f;

    for (int kB = 0; kB < DIN; kB += GBK) {
        {
            int kk = tid >> 4, cc = (tid & 15) * 4;
            float4 v = *(const float4*)&g_wpack[(kB + kk) * COLS_PAD + cBase + cc];
            *(float4*)&Ws[kk][cc] = v;
        }
        #pragma unroll
        for (int ch = 0; ch < 2; ch++) {
            int idx = tid + ch * 256;
            int kk = idx >> 5, rr = (idx & 31) * 4;
            float4 v = *(const float4*)&g_xT[(kB + kk) * NROWS + rBase + rr];
            *(float4*)&Xs[kk][rr] = v;
        }
        __syncthreads();
        #pragma unroll
        for (int kk = 0; kk < GBK; kk++) {
            float a[4], bb[8];
            *(float4*)&a[0]  = *(const float4*)&Ws[kk][ty * 4];
            *(float4*)&bb[0] = *(const float4*)&Xs[kk][tx * 4];
            *(float4*)&bb[4] = *(const float4*)&Xs[kk][64 + tx * 4];
            #pragma unroll
            for (int i = 0; i < 4; i++)
                #pragma unroll
                for (int j = 0; j < 8; j++)
                    acc[i][j] = fmaf(a[i], bb[j], acc[i][j]);
        }
        __syncthreads();
    }

    #pragma unroll
    for (int i = 0; i < 4; i++) {
        int c = cBase + ty * 4 + i;
        float bv = g_bias[c];
        bool act = (c < 768);
        float o[8];
        #pragma unroll
        for (int j = 0; j < 8; j++) {
            float v = acc[i][j];
            if (act) v = fminf(softplusf(v + bv), 0.15f);
            o[j] = v;
        }
        *(float4*)&g_scratch[c * NROWS + rBase + tx * 4]      = *(float4*)&o[0];
        *(float4*)&g_scratch[c * NROWS + rBase + 64 + tx * 4] = *(float4*)&o[4];
    }
}

// ---------------- kernel 2: SSM — one (b,d) per block, 2 s-states per phase ----------------
// 256 threads; thread owns 1x4 px for TWO s values. 16 barrier phases (was 32).
#define SHS 36
__global__ __launch_bounds__(256, 2) void ssm_kernel(const float* __restrict__ conv_w,
                                                     const float* __restrict__ ralpha,
                                                     const float* __restrict__ rbeta,
                                                     const float* __restrict__ Dparam,
                                                     const float* __restrict__ A_log,
                                                     float* __restrict__ y) {
    __shared__ float shR[2][2][32][SHS];   // [s-slot][buf][row][col]
    __shared__ float shI[2][2][32][SHS];

    int d   = blockIdx.x;
    int b   = blockIdx.y;
    int tid = threadIdx.x;
    int row   = tid >> 3;
    int lane8 = tid & 7;
    int pcb   = lane8 * 4;
    int nb    = row * 32 + pcb;
    int row0  = b * NTOK;

    int rm = (row > 0)  ? row - 1 : 0;
    int rp = (row < 31) ? row + 1 : 31;
    int cl = (pcb > 0)  ? pcb - 1 : 0;
    int cr = (pcb < 28) ? pcb + 4 : 31;

    float w[9];
    #pragma unroll
    for (int i = 0; i < 9; i++) w[i] = conv_w[d * 9 + i];
    float alpha = ralpha[d];
    float beta  = rbeta[d];
    float Dp    = Dparam[d];

    float xv[4], ds[4], dd[4], yacc[4];
    {
        float4 t;
        t = *(const float4*)&g_xT[d * NROWS + row0 + nb];
        xv[0]=t.x; xv[1]=t.y; xv[2]=t.z; xv[3]=t.w;
        t = *(const float4*)&g_scratch[d * NROWS + row0 + nb];
        ds[0]=t.x; ds[1]=t.y; ds[2]=t.z; ds[3]=t.w;
        t = *(const float4*)&g_scratch[(384 + d) * NROWS + row0 + nb];
        dd[0]=t.x; dd[1]=t.y; dd[2]=t.z; dd[3]=t.w;
    }
    #pragma unroll
    for (int j = 0; j < 4; j++) yacc[j] = xv[j] * Dp;

    int buf = 0;
    for (int p = 0; p < 8; p++) {
        float A[2], u[2][4], hr[2][4], hi[2][4];
        #pragma unroll
        for (int sp = 0; sp < 2; sp++) {
            int s = 2 * p + sp;
            A[sp] = -softplusf(A_log[d * SST + s]);
            float4 t = *(const float4*)&g_scratch[(768 + s) * NROWS + row0 + nb];
            u[sp][0] = xv[0] * t.x; u[sp][1] = xv[1] * t.y;
            u[sp][2] = xv[2] * t.z; u[sp][3] = xv[3] * t.w;
            #pragma unroll
            for (int j = 0; j < 4; j++) { hr[sp][j] = u[sp][j]; hi[sp][j] = 0.f; }
        }

        #pragma unroll
        for (int step = 0; step < 2; step++) {
            // publish both s grids
            #pragma unroll
            for (int sp = 0; sp < 2; sp++) {
                *(float4*)&shR[sp][buf][row][pcb] =
                    make_float4(hr[sp][0], hr[sp][1], hr[sp][2], hr[sp][3]);
                *(float4*)&shI[sp][buf][row][pcb] =
                    make_float4(hi[sp][0], hi[sp][1], hi[sp][2], hi[sp][3]);
            }
            __syncthreads();   // single barrier per phase, serves both s

            #pragma unroll
            for (int sp = 0; sp < 2; sp++) {
                float4 tR4 = *(const float4*)&shR[sp][buf][rm][pcb];
                float  tRl = shR[sp][buf][rm][cl];
                float  tRr = shR[sp][buf][rm][cr];
                float4 bR4 = *(const float4*)&shR[sp][buf][rp][pcb];
                float  bRl = shR[sp][buf][rp][cl];
                float  bRr = shR[sp][buf][rp][cr];
                float4 tI4 = *(const float4*)&shI[sp][buf][rm][pcb];
                float  tIl = shI[sp][buf][rm][cl];
                float  tIr = shI[sp][buf][rm][cr];
                float4 bI4 = *(const float4*)&shI[sp][buf][rp][pcb];
                float  bIl = shI[sp][buf][rp][cl];
                float  bIr = shI[sp][buf][rp][cr];

                float mRl = __shfl_up_sync(0xffffffffu,   hr[sp][3], 1);
                float mRr = __shfl_down_sync(0xffffffffu, hr[sp][0], 1);
                float mIl = __shfl_up_sync(0xffffffffu,   hi[sp][3], 1);
                float mIr = __shfl_down_sync(0xffffffffu, hi[sp][0], 1);
                if (lane8 == 0) { mRl = hr[sp][0]; mIl = hi[sp][0]; }
                if (lane8 == 7) { mRr = hr[sp][3]; mIr = hi[sp][3]; }

                float topR[6] = {tRl, tR4.x, tR4.y, tR4.z, tR4.w, tRr};
                float midR[6] = {mRl, hr[sp][0], hr[sp][1], hr[sp][2], hr[sp][3], mRr};
                float botR[6] = {bRl, bR4.x, bR4.y, bR4.z, bR4.w, bRr};
                float topI[6] = {tIl, tI4.x, tI4.y, tI4.z, tI4.w, tIr};
                float midI[6] = {mIl, hi[sp][0], hi[sp][1], hi[sp][2], hi[sp][3], mIr};
                float botI[6] = {bIl, bI4.x, bI4.y, bI4.z, bI4.w, bIr};

                float nhr[4], nhi[4];
                #pragma unroll
                for (int j = 0; j < 4; j++) {
                    float lapR =      w[0] * topR[j];
                    lapR = fmaf(w[1], topR[j+1], lapR);
                    lapR = fmaf(w[2], topR[j+2], lapR);
                    lapR = fmaf(w[3], midR[j],   lapR);
                    lapR = fmaf(w[4], midR[j+1], lapR);
                    lapR = fmaf(w[5], midR[j+2], lapR);
                    lapR = fmaf(w[6], botR[j],   lapR);
                    lapR = fmaf(w[7], botR[j+1], lapR);
                    lapR = fmaf(w[8], botR[j+2], lapR);
                    float lapI =      w[0] * topI[j];
                    lapI = fmaf(w[1], topI[j+1], lapI);
                    lapI = fmaf(w[2], topI[j+2], lapI);
                    lapI = fmaf(w[3], midI[j],   lapI);
                    lapI = fmaf(w[4], midI[j+1], lapI);
                    lapI = fmaf(w[5], midI[j+2], lapI);
                    lapI = fmaf(w[6], botI[j],   lapI);
                    lapI = fmaf(w[7], botI[j+1], lapI);
                    lapI = fmaf(w[8], botI[j+2], lapI);

                    float h2 = fmaf(hr[sp][j], hr[sp][j], hi[sp][j] * hi[sp][j]);
                    float rs = alpha - beta * h2;
                    float f1r = ds[j] * fmaf(A[sp], hr[sp][j], u[sp][j]);
                    float f1i = ds[j] * (A[sp] * hi[sp][j]);
                    float sumr = f1r - dd[j] * lapI + hr[sp][j] * rs;
                    float sumi = f1i + dd[j] * lapR + hi[sp][j] * rs;
                    nhr[j] = fmaf(0.5f, sumr, hr[sp][j]);
                    nhi[j] = fmaf(0.5f, sumi, hi[sp][j]);
                }
                #pragma unroll
                for (int j = 0; j < 4; j++) { hr[sp][j] = nhr[j]; hi[sp][j] = nhi[j]; }
            }
            buf ^= 1;
        }

        // output projection accumulate for both s
        #pragma unroll
        for (int sp = 0; sp < 2; sp++) {
            int s = 2 * p + sp;
            float4 crv = *(const float4*)&g_scratch[(784 + s) * NROWS + row0 + nb];
            float4 civ = *(const float4*)&g_scratch[(800 + s) * NROWS + row0 + nb];
            yacc[0] = fmaf(hr[sp][0], crv.x, fmaf(hi[sp][0], civ.x, yacc[0]));
            yacc[1] = fmaf(hr[sp][1], crv.y, fmaf(hi[sp][1], civ.y, yacc[1]));
            yacc[2] = fmaf(hr[sp][2], crv.z, fmaf(hi[sp][2], civ.z, yacc[2]));
            yacc[3] = fmaf(hr[sp][3], crv.w, fmaf(hi[sp][3], civ.w, yacc[3]));
        }
    }

    #pragma unroll
    for (int j = 0; j < 4; j++)
        y[(row0 + nb + j) * DIN + d] = yacc[j];
}

// ---------------- launch ----------------
extern "C" void kernel_launch(void* const* d_in, const int* in_sizes, int n_in,
                              void* d_out, int out_size) {
    const float* x      = (const float*)d_in[0];
    const float* dtsW   = (const float*)d_in[1];
    const float* dtsb   = (const float*)d_in[2];
    const float* dtdW   = (const float*)d_in[3];
    const float* dtdb   = (const float*)d_in[4];
    const float* BW     = (const float*)d_in[5];
    const float* CrW    = (const float*)d_in[6];
    const float* CiW    = (const float*)d_in[7];
    const float* Dparam = (const float*)d_in[8];
    const float* A_log  = (const float*)d_in[9];
    const float* conv_w = (const float*)d_in[10];
    const float* ralpha = (const float*)d_in[11];
    const float* rbeta  = (const float*)d_in[12];
    float* y = (float*)d_out;

    pack_kernel<<<(DIN * COLS_PAD + 255) / 256, 256>>>(dtsW, dtsb, dtdW, dtdb, BW, CrW, CiW);
    transpose_x<<<dim3(DIN / 32, NROWS / 32), dim3(32, 8)>>>(x);
    gemm_kernel<<<dim3(COLS_PAD / GBM, NROWS / GBN), 256>>>();
    ssm_kernel<<<dim3(DIN, BSZ), 256>>>(conv_w, ralpha, rbeta, Dparam, A_log, y);
}

// round 6
// speedup vs baseline: 1.1915x; 1.1915x over previous
#include <cuda_runtime.h>
#include <math.h>

#define BSZ   4
#define NTOK  1024
#define DIN   384
#define SST   16
#define NROWS 4096
#define NCOLS 816
#define COLS_PAD 832

__device__ __align__(16) float g_wpack[DIN * COLS_PAD];
__device__ __align__(16) float g_bias[COLS_PAD];
__device__ __align__(16) float g_xT[DIN * NROWS];
__device__ __align__(16) float g_scratch[COLS_PAD * NROWS];

__device__ __forceinline__ float softplusf(float z) {
    return (z > 20.f) ? z : log1pf(expf(z));
}

// ---------------- packed f32x2 helpers (sm_103a FFMA2 path, PTX-only) ----------------
typedef unsigned long long f2;
__device__ __forceinline__ f2 pk(float lo, float hi) {
    f2 r; asm("mov.b64 %0,{%1,%2};" : "=l"(r) : "f"(lo), "f"(hi)); return r;
}
__device__ __forceinline__ void up2(f2 v, float& lo, float& hi) {
    asm("mov.b64 {%0,%1},%2;" : "=f"(lo), "=f"(hi) : "l"(v));
}
__device__ __forceinline__ f2 fma2(f2 a, f2 b, f2 c) {
    f2 r; asm("fma.rn.f32x2 %0,%1,%2,%3;" : "=l"(r) : "l"(a), "l"(b), "l"(c)); return r;
}
__device__ __forceinline__ f2 mul2(f2 a, f2 b) {
    f2 r; asm("mul.rn.f32x2 %0,%1,%2;" : "=l"(r) : "l"(a), "l"(b)); return r;
}

// ---------------- kernel 0a: pack weights k-major + bias ----------------
__global__ void pack_kernel(const float* __restrict__ dtsW, const float* __restrict__ dtsb,
                            const float* __restrict__ dtdW, const float* __restrict__ dtdb,
                            const float* __restrict__ BW,   const float* __restrict__ CrW,
                            const float* __restrict__ CiW) {
    int i = blockIdx.x * blockDim.x + threadIdx.x;
    if (i >= DIN * COLS_PAD) return;
    int k = i / COLS_PAD;
    int c = i % COLS_PAD;
    float v = 0.f;
    if      (c < 384) v = dtsW[c * DIN + k];
    else if (c < 768) v = dtdW[(c - 384) * DIN + k];
    else if (c < 784) v = BW [k * SST + (c - 768)];
    else if (c < 800) v = CrW[k * SST + (c - 784)];
    else if (c < 816) v = CiW[k * SST + (c - 800)];
    g_wpack[i] = v;
    if (k == 0) {
        float bv = 0.f;
        if (c < 384)      bv = dtsb[c];
        else if (c < 768) bv = dtdb[c - 384];
        g_bias[c] = bv;
    }
}

// ---------------- kernel 0b: transpose x -> xT[d][row] ----------------
__global__ void transpose_x(const float* __restrict__ x) {
    __shared__ float tile[32][33];
    int kb = blockIdx.x * 32;
    int rb = blockIdx.y * 32;
    int tx = threadIdx.x, ty = threadIdx.y;
    #pragma unroll
    for (int i = ty; i < 32; i += 8)
        tile[i][tx] = x[(rb + i) * DIN + kb + tx];
    __syncthreads();
    #pragma unroll
    for (int i = ty; i < 32; i += 8)
        g_xT[(kb + i) * NROWS + rb + tx] = tile[tx][i];
}

// ---------------- kernel 1: fused GEMM, packed accumulators ----------------
#define GBM 64
#define GBN 128
#define GBK 16
__global__ __launch_bounds__(256) void gemm_kernel() {
    __shared__ float Ws[GBK][68];
    __shared__ float Xs[GBK][GBN + 4];
    int tid = threadIdx.x;
    int tx = tid & 15;
    int ty = tid >> 4;
    int cBase = blockIdx.x * GBM;
    int rBase = blockIdx.y * GBN;

    f2 acc2[4][4];   // [col i][row-pair j] : (row 2j, row 2j+1)
    #pragma unroll
    for (int i = 0; i < 4; i++)
        #pragma unroll
        for (int j = 0; j < 4; j++) acc2[i][j] = pk(0.f, 0.f);

    for (int kB = 0; kB < DIN; kB += GBK) {
        {
            int kk = tid >> 4, cc = (tid & 15) * 4;
            float4 v = *(const float4*)&g_wpack[(kB + kk) * COLS_PAD + cBase + cc];
            *(float4*)&Ws[kk][cc] = v;
        }
        #pragma unroll
        for (int ch = 0; ch < 2; ch++) {
            int idx = tid + ch * 256;
            int kk = idx >> 5, rr = (idx & 31) * 4;
            float4 v = *(const float4*)&g_xT[(kB + kk) * NROWS + rBase + rr];
            *(float4*)&Xs[kk][rr] = v;
        }
        __syncthreads();
        #pragma unroll
        for (int kk = 0; kk < GBK; kk++) {
            float a[4];
            *(float4*)&a[0] = *(const float4*)&Ws[kk][ty * 4];
            float4 x0 = *(const float4*)&Xs[kk][tx * 4];
            float4 x1 = *(const float4*)&Xs[kk][64 + tx * 4];
            f2 b2[4] = { pk(x0.x, x0.y), pk(x0.z, x0.w), pk(x1.x, x1.y), pk(x1.z, x1.w) };
            #pragma unroll
            for (int i = 0; i < 4; i++) {
                f2 a2 = pk(a[i], a[i]);
                #pragma unroll
                for (int j = 0; j < 4; j++)
                    acc2[i][j] = fma2(a2, b2[j], acc2[i][j]);
            }
        }
        __syncthreads();
    }

    #pragma unroll
    for (int i = 0; i < 4; i++) {
        int c = cBase + ty * 4 + i;
        float bv = g_bias[c];
        bool act = (c < 768);
        float o[8];
        #pragma unroll
        for (int j = 0; j < 4; j++) up2(acc2[i][j], o[2 * j], o[2 * j + 1]);
        #pragma unroll
        for (int j = 0; j < 8; j++) {
            float v = o[j];
            if (act) v = fminf(softplusf(v + bv), 0.15f);
            o[j] = v;
        }
        *(float4*)&g_scratch[c * NROWS + rBase + tx * 4]      = *(float4*)&o[0];
        *(float4*)&g_scratch[c * NROWS + rBase + 64 + tx * 4] = *(float4*)&o[4];
    }
}

// ---------------- kernel 2: SSM — 128 threads per (b,d), 2x4 px/thread, packed (re,im) ----------------
#define SHS 36
__device__ __forceinline__ f2 pointwise(f2 h, f2 lap, float uj, float dsj, float ddj,
                                        f2 A2, float alpha, float beta) {
    float hrj, hij; up2(h, hrj, hij);
    float h2 = fmaf(hrj, hrj, hij * hij);
    float rs = fmaf(-beta, h2, alpha);
    f2 f1 = mul2(pk(dsj, dsj), fma2(A2, h, pk(uj, 0.f)));
    float lr, li; up2(lap, lr, li);
    f2 sum = fma2(pk(ddj, ddj), pk(-li, lr), f1);
    sum = fma2(h, pk(rs, rs), sum);
    return fma2(pk(0.5f, 0.5f), sum, h);
}

__global__ __launch_bounds__(128, 4) void ssm_kernel(const float* __restrict__ conv_w,
                                                     const float* __restrict__ ralpha,
                                                     const float* __restrict__ rbeta,
                                                     const float* __restrict__ Dparam,
                                                     const float* __restrict__ A_log,
                                                     float* __restrict__ y) {
    __shared__ float shR[2][32][SHS];
    __shared__ float shI[2][32][SHS];

    int d   = blockIdx.x;
    int b   = blockIdx.y;
    int t   = threadIdx.x;          // 0..127
    int R0  = (t >> 3) * 2;         // top row of owned pair
    int lane8 = t & 7;
    int pcb = lane8 * 4;
    int row0 = b * NTOK;
    int n0 = R0 * 32 + pcb;
    int n1 = n0 + 32;

    int rm = (R0 > 0)      ? R0 - 1 : 0;
    int rp = (R0 + 2 < 32) ? R0 + 2 : 31;
    int cl = (pcb > 0)  ? pcb - 1 : 0;
    int cr = (pcb < 28) ? pcb + 4 : 31;

    f2 w2[9];
    #pragma unroll
    for (int i = 0; i < 9; i++) { float wv = conv_w[d * 9 + i]; w2[i] = pk(wv, wv); }
    float alpha = ralpha[d];
    float beta  = rbeta[d];
    float Dp    = Dparam[d];

    float xv[8], ds[8], dd[8];
    {
        float4 a = *(const float4*)&g_xT[d * NROWS + row0 + n0];
        float4 c = *(const float4*)&g_xT[d * NROWS + row0 + n1];
        xv[0]=a.x; xv[1]=a.y; xv[2]=a.z; xv[3]=a.w;
        xv[4]=c.x; xv[5]=c.y; xv[6]=c.z; xv[7]=c.w;
        a = *(const float4*)&g_scratch[d * NROWS + row0 + n0];
        c = *(const float4*)&g_scratch[d * NROWS + row0 + n1];
        ds[0]=a.x; ds[1]=a.y; ds[2]=a.z; ds[3]=a.w;
        ds[4]=c.x; ds[5]=c.y; ds[6]=c.z; ds[7]=c.w;
        a = *(const float4*)&g_scratch[(384 + d) * NROWS + row0 + n0];
        c = *(const float4*)&g_scratch[(384 + d) * NROWS + row0 + n1];
        dd[0]=a.x; dd[1]=a.y; dd[2]=a.z; dd[3]=a.w;
        dd[4]=c.x; dd[5]=c.y; dd[6]=c.z; dd[7]=c.w;
    }

    f2 yac[8];
    #pragma unroll
    for (int j = 0; j < 8; j++) yac[j] = pk(0.f, 0.f);

    int buf = 0;
    for (int s = 0; s < SST; s++) {
        float A = -softplusf(A_log[d * SST + s]);
        f2 A2 = pk(A, A);
        float u[8];
        f2 hc[8];
        {
            float4 a = *(const float4*)&g_scratch[(768 + s) * NROWS + row0 + n0];
            float4 c = *(const float4*)&g_scratch[(768 + s) * NROWS + row0 + n1];
            u[0]=xv[0]*a.x; u[1]=xv[1]*a.y; u[2]=xv[2]*a.z; u[3]=xv[3]*a.w;
            u[4]=xv[4]*c.x; u[5]=xv[5]*c.y; u[6]=xv[6]*c.z; u[7]=xv[7]*c.w;
        }
        #pragma unroll
        for (int j = 0; j < 8; j++) hc[j] = pk(u[j], 0.f);

        #pragma unroll
        for (int step = 0; step < 2; step++) {
            // publish owned rows (scalar planes, conflict-free)
            {
                float a0,b0,a1,b1,a2,b2,a3,b3;
                up2(hc[0],a0,b0); up2(hc[1],a1,b1); up2(hc[2],a2,b2); up2(hc[3],a3,b3);
                *(float4*)&shR[buf][R0][pcb] = make_float4(a0,a1,a2,a3);
                *(float4*)&shI[buf][R0][pcb] = make_float4(b0,b1,b2,b3);
                up2(hc[4],a0,b0); up2(hc[5],a1,b1); up2(hc[6],a2,b2); up2(hc[7],a3,b3);
                *(float4*)&shR[buf][R0+1][pcb] = make_float4(a0,a1,a2,a3);
                *(float4*)&shI[buf][R0+1][pcb] = make_float4(b0,b1,b2,b3);
            }
            __syncthreads();

            // halo rows from shared, packed into (re,im) pairs
            float4 tR4 = *(const float4*)&shR[buf][rm][pcb];
            float  tRl = shR[buf][rm][cl];
            float  tRr = shR[buf][rm][cr];
            float4 tI4 = *(const float4*)&shI[buf][rm][pcb];
            float  tIl = shI[buf][rm][cl];
            float  tIr = shI[buf][rm][cr];
            float4 bR4 = *(const float4*)&shR[buf][rp][pcb];
            float  bRl = shR[buf][rp][cl];
            float  bRr = shR[buf][rp][cr];
            float4 bI4 = *(const float4*)&shI[buf][rp][pcb];
            float  bIl = shI[buf][rp][cl];
            float  bIr = shI[buf][rp][cr];

            f2 T[6]  = { pk(tRl,tIl), pk(tR4.x,tI4.x), pk(tR4.y,tI4.y),
                         pk(tR4.z,tI4.z), pk(tR4.w,tI4.w), pk(tRr,tIr) };
            f2 Bw[6] = { pk(bRl,bIl), pk(bR4.x,bI4.x), pk(bR4.y,bI4.y),
                         pk(bR4.z,bI4.z), pk(bR4.w,bI4.w), pk(bRr,bIr) };

            // horizontal edge taps via shuffle on scalar halves
            float h0r,h0i,h3r,h3i,h4r,h4i,h7r,h7i;
            up2(hc[0],h0r,h0i); up2(hc[3],h3r,h3i);
            up2(hc[4],h4r,h4i); up2(hc[7],h7r,h7i);
            float e0lr = __shfl_up_sync(0xffffffffu,   h3r, 1);
            float e0li = __shfl_up_sync(0xffffffffu,   h3i, 1);
            float e0rr = __shfl_down_sync(0xffffffffu, h0r, 1);
            float e0ri = __shfl_down_sync(0xffffffffu, h0i, 1);
            float e1lr = __shfl_up_sync(0xffffffffu,   h7r, 1);
            float e1li = __shfl_up_sync(0xffffffffu,   h7i, 1);
            float e1rr = __shfl_down_sync(0xffffffffu, h4r, 1);
            float e1ri = __shfl_down_sync(0xffffffffu, h4i, 1);
            if (lane8 == 0) { e0lr=h0r; e0li=h0i; e1lr=h4r; e1li=h4i; }
            if (lane8 == 7) { e0rr=h3r; e0ri=h3i; e1rr=h7r; e1ri=h7i; }

            f2 M0[6] = { pk(e0lr,e0li), hc[0], hc[1], hc[2], hc[3], pk(e0rr,e0ri) };
            f2 M1[6] = { pk(e1lr,e1li), hc[4], hc[5], hc[6], hc[7], pk(e1rr,e1ri) };

            f2 hn[8];
            #pragma unroll
            for (int c = 0; c < 4; c++) {
                // row 0 pixel: taps T / M0 / M1
                f2 lap = mul2(w2[0], T[c]);
                lap = fma2(w2[1], T[c+1], lap);
                lap = fma2(w2[2], T[c+2], lap);
                lap = fma2(w2[3], M0[c],   lap);
                lap = fma2(w2[4], M0[c+1], lap);
                lap = fma2(w2[5], M0[c+2], lap);
                lap = fma2(w2[6], M1[c],   lap);
                lap = fma2(w2[7], M1[c+1], lap);
                lap = fma2(w2[8], M1[c+2], lap);
                hn[c] = pointwise(hc[c], lap, u[c], ds[c], dd[c], A2, alpha, beta);

                // row 1 pixel: taps M0 / M1 / Bw
                f2 lap2 = mul2(w2[0], M0[c]);
                lap2 = fma2(w2[1], M0[c+1], lap2);
                lap2 = fma2(w2[2], M0[c+2], lap2);
                lap2 = fma2(w2[3], M1[c],   lap2);
                lap2 = fma2(w2[4], M1[c+1], lap2);
                lap2 = fma2(w2[5], M1[c+2], lap2);
                lap2 = fma2(w2[6], Bw[c],   lap2);
                lap2 = fma2(w2[7], Bw[c+1], lap2);
                lap2 = fma2(w2[8], Bw[c+2], lap2);
                hn[4+c] = pointwise(hc[4+c], lap2, u[4+c], ds[4+c], dd[4+c], A2, alpha, beta);
            }
            #pragma unroll
            for (int j = 0; j < 8; j++) hc[j] = hn[j];
            buf ^= 1;
        }

        // output projection accumulate: yac += h * (Cr, Ci) — packed pair dot
        {
            float4 c0 = *(const float4*)&g_scratch[(784 + s) * NROWS + row0 + n0];
            float4 c1 = *(const float4*)&g_scratch[(784 + s) * NROWS + row0 + n1];
            float4 i0 = *(const float4*)&g_scratch[(800 + s) * NROWS + row0 + n0];
            float4 i1 = *(const float4*)&g_scratch[(800 + s) * NROWS + row0 + n1];
            yac[0] = fma2(hc[0], pk(c0.x, i0.x), yac[0]);
            yac[1] = fma2(hc[1], pk(c0.y, i0.y), yac[1]);
            yac[2] = fma2(hc[2], pk(c0.z, i0.z), yac[2]);
            yac[3] = fma2(hc[3], pk(c0.w, i0.w), yac[3]);
            yac[4] = fma2(hc[4], pk(c1.x, i1.x), yac[4]);
            yac[5] = fma2(hc[5], pk(c1.y, i1.y), yac[5]);
            yac[6] = fma2(hc[6], pk(c1.z, i1.z), yac[6]);
            yac[7] = fma2(hc[7], pk(c1.w, i1.w), yac[7]);
        }
    }

    #pragma unroll
    for (int j = 0; j < 4; j++) {
        float ar, ai; up2(yac[j], ar, ai);
        y[(row0 + n0 + j) * DIN + d] = ar + ai + xv[j] * Dp;
        up2(yac[4 + j], ar, ai);
        y[(row0 + n1 + j) * DIN + d] = ar + ai + xv[4 + j] * Dp;
    }
}

// ---------------- launch ----------------
extern "C" void kernel_launch(void* const* d_in, const int* in_sizes, int n_in,
                              void* d_out, int out_size) {
    const float* x      = (const float*)d_in[0];
    const float* dtsW   = (const float*)d_in[1];
    const float* dtsb   = (const float*)d_in[2];
    const float* dtdW   = (const float*)d_in[3];
    const float* dtdb   = (const float*)d_in[4];
    const float* BW     = (const float*)d_in[5];
    const float* CrW    = (const float*)d_in[6];
    const float* CiW    = (const float*)d_in[7];
    const float* Dparam = (const float*)d_in[8];
    const float* A_log  = (const float*)d_in[9];
    const float* conv_w = (const float*)d_in[10];
    const float* ralpha = (const float*)d_in[11];
    const float* rbeta  = (const float*)d_in[12];
    float* y = (float*)d_out;

    pack_kernel<<<(DIN * COLS_PAD + 255) / 256, 256>>>(dtsW, dtsb, dtdW, dtdb, BW, CrW, CiW);
    transpose_x<<<dim3(DIN / 32, NROWS / 32), dim3(32, 8)>>>(x);
    gemm_kernel<<<dim3(COLS_PAD / GBM, NROWS / GBN), 256>>>();
    ssm_kernel<<<dim3(DIN, BSZ), 128>>>(conv_w, ralpha, rbeta, Dparam, A_log, y);
}